// round 13
// baseline (speedup 1.0000x reference)
#include <cuda_runtime.h>
#include <math.h>

// MultiActorCriticRNN: A=4, T=128, B=256, OBS=H=128, ACT=8
#define NA   4
#define NT   128
#define NB   256
#define NH   128
#define NOBS 128
#define NACT 8
#define G3   384   // 3*H

// Output layout: hT [A,B,H] | mean [A,T,B,ACT] | std [A,ACT] | value [A,T,B]
#define O_HT   0
#define O_MEAN 131072
#define O_STD  1179648
#define O_VAL  1179680

typedef unsigned long long ull;

// packed f32x2 helpers (FFMA2 path; exact fp32 per lane)
#define PACKF2(d, lo, hi) \
    asm("mov.b64 %0, {%1, %2};" : "=l"(d) : "f"(lo), "f"(hi))
#define UNPACKF2(lo, hi, d) \
    asm("mov.b64 {%0, %1}, %2;" : "=f"(lo), "=f"(hi) : "l"(d))
#define FMA2(d, a, b) \
    asm("fma.rn.f32x2 %0, %1, %2, %0;" : "+l"(d) : "l"(a), "l"(b))

// Scratch (static device globals -- allocation-free kernel_launch)
__device__ float g_xi[(size_t)NA * NT * NB * G3];   // 50,331,648 floats
__device__ float g_ys[(size_t)NA * NT * NB * NH];   // 16,777,216 floats
__device__ int   g_done_mode;                       // 0=int32, 1=u8/bool, 2=float32

// ---------------------------------------------------------------------------
// done-dtype detection (recomputed fresh every launch => deterministic)
// ---------------------------------------------------------------------------
__global__ void k_dzero() { g_done_mode = 0; }

__global__ void k_ddet(const unsigned int* __restrict__ w, int nwords)
{
    int mode = 0;
    for (int i = blockIdx.x * blockDim.x + threadIdx.x; i < nwords;
         i += gridDim.x * blockDim.x) {
        unsigned int v = w[i];
        if (v > 1u) mode = (v == 0x3F800000u) ? 2 : ((mode == 2) ? 2 : 1);
    }
    if (mode) atomicMax(&g_done_mode, mode);
}

__device__ __forceinline__ float read_done(const void* done, size_t idx, int mode)
{
    if (mode == 1) return ((const unsigned char*)done)[idx] ? 1.f : 0.f;
    if (mode == 2) return (((const float*)done)[idx] != 0.f) ? 1.f : 0.f;
    return ((const int*)done)[idx] ? 1.f : 0.f;
}

// ---------------------------------------------------------------------------
// 64x64 output tile, K=128 microkernel using packed f32x2 FMAs.
// Xs: [64][132] padded, Ws: [128][64]. 256 threads as 16x16; 4x4 per thread.
// Accumulators packed over column pairs; W pairs come free from LDS.128.
// ---------------------------------------------------------------------------
__device__ __forceinline__ void mm_tile2(const float* __restrict__ Xs,
                                         const float* __restrict__ Ws,
                                         float accf[4][4], int ty, int tx)
{
    const int r0 = 4 * ty, c0 = 4 * tx;
    ull acc[4][2];
#pragma unroll
    for (int i = 0; i < 4; i++) { acc[i][0] = 0ull; acc[i][1] = 0ull; }

#pragma unroll 4
    for (int k = 0; k < 128; k += 4) {
        float4 x[4];
#pragma unroll
        for (int i = 0; i < 4; i++) x[i] = *(const float4*)&Xs[(r0 + i) * 132 + k];
        const float* xv = (const float*)x;
#pragma unroll
        for (int kk = 0; kk < 4; kk++) {
            ulonglong2 w = *(const ulonglong2*)&Ws[(k + kk) * 64 + c0];
#pragma unroll
            for (int i = 0; i < 4; i++) {
                float xs = xv[i * 4 + kk];
                ull xp; PACKF2(xp, xs, xs);
                FMA2(acc[i][0], xp, w.x);
                FMA2(acc[i][1], xp, w.y);
            }
        }
    }
#pragma unroll
    for (int i = 0; i < 4; i++) {
        UNPACKF2(accf[i][0], accf[i][1], acc[i][0]);
        UNPACKF2(accf[i][2], accf[i][3], acc[i][1]);
    }
}

// ---------------------------------------------------------------------------
// K1: xi = tanh(obs @ We + be) @ Wi + bi     -> g_xi
// ---------------------------------------------------------------------------
__global__ void __launch_bounds__(256)
k_embed(const float* __restrict__ obs, const float* __restrict__ We,
        const float* __restrict__ be,  const float* __restrict__ Wi,
        const float* __restrict__ bi)
{
    extern __shared__ float sm[];
    float* obs_s = sm;                    // 64*132
    float* emb_s = obs_s + 64 * 132;      // 64*132
    float* w_s   = emb_s + 64 * 132;      // 128*64

    const int a   = blockIdx.y;
    const int r0  = blockIdx.x * 64;
    const int tid = threadIdx.x;
    const int ty  = tid >> 4, tx = tid & 15;

    const float* obsA = obs + ((size_t)a * NT * NB + r0) * NOBS;
    for (int i = tid; i < 64 * 32; i += 256) {
        int r = i >> 5, c4 = i & 31;
        ((float4*)&obs_s[r * 132])[c4] = ((const float4*)&obsA[(size_t)r * 128])[c4];
    }

    const float* WeA = We + (size_t)a * 128 * 128;
    for (int cc = 0; cc < 2; cc++) {
        __syncthreads();
        for (int i = tid; i < 128 * 16; i += 256) {
            int k = i >> 4, c4 = i & 15;
            ((float4*)&w_s[k * 64])[c4] = ((const float4*)&WeA[k * 128 + cc * 64])[c4];
        }
        __syncthreads();
        float acc[4][4];
        mm_tile2(obs_s, w_s, acc, ty, tx);
#pragma unroll
        for (int i = 0; i < 4; i++)
#pragma unroll
            for (int j = 0; j < 4; j++) {
                int c = cc * 64 + 4 * tx + j;
                emb_s[(4 * ty + i) * 132 + c] = tanhf(acc[i][j] + be[a * 128 + c]);
            }
    }

    const float* WiA = Wi + (size_t)a * 128 * G3;
    float* xiA = g_xi + ((size_t)a * NT * NB + r0) * G3;
    for (int cc = 0; cc < 6; cc++) {
        __syncthreads();
        for (int i = tid; i < 128 * 16; i += 256) {
            int k = i >> 4, c4 = i & 15;
            ((float4*)&w_s[k * 64])[c4] = ((const float4*)&WiA[k * G3 + cc * 64])[c4];
        }
        __syncthreads();
        float acc[4][4];
        mm_tile2(emb_s, w_s, acc, ty, tx);
#pragma unroll
        for (int i = 0; i < 4; i++)
#pragma unroll
            for (int j = 0; j < 4; j++) {
                int c = cc * 64 + 4 * tx + j;
                xiA[(size_t)(4 * ty + i) * G3 + c] = acc[i][j] + bi[a * G3 + c];
            }
    }
}

// ---------------------------------------------------------------------------
// K2: sequential GRU. grid (32, 4): x = 8-batch-row tile, y = agent. 256 thr.
// Wh resident in smem. h stored COLUMN-MAJOR h2_s[k][8] so row-pairs load as
// broadcast LDS.64 and feed packed FFMA2 (rows packed, W splatted).
// Two independent 128-thread halves (4 rows each), named-barrier synced.
// done folded into registers; xi straight from gmem into registers.
// smem: Wh_s[128*384] | h2_s[128*8] | bhn_s[128]
// ---------------------------------------------------------------------------
__global__ void __launch_bounds__(256)
k_gru(const float* __restrict__ hstate, const float* __restrict__ Wh,
      const float* __restrict__ bhn, const void* __restrict__ done,
      float* __restrict__ out)
{
    extern __shared__ float sm[];
    float* Wh_s  = sm;                    // 128*384
    float* h2_s  = Wh_s + 128 * G3;       // 128 cols x 8 rows (col-major)
    float* bhn_s = h2_s + 128 * 8;        // 128

    const int a   = blockIdx.y;
    const int b0  = blockIdx.x * 8;
    const int tid = threadIdx.x;
    const int ty  = tid >> 7;              // half: rows 4*ty..4*ty+3
    const int tx  = tid & 127;             // column j
    const int dmode = g_done_mode;

    // load Wh + bhn
    const float* WhA = Wh + (size_t)a * 128 * G3;
    for (int i = tid; i < 128 * 96; i += 256)
        ((float4*)Wh_s)[i] = ((const float4*)WhA)[i];
    if (tid < 128) bhn_s[tid] = bhn[a * 128 + tid];
    // h0 -> column-major h2_s[c*8 + r]
    for (int i = tid; i < 1024; i += 256) {
        int c = i >> 3, r = i & 7;
        h2_s[i] = hstate[((size_t)a * NB + b0 + r) * NH + c];
    }
    __syncthreads();

    const int bar = 1 + ty;                // named barrier per half
    float* ysA = g_ys + ((size_t)a * NT * NB + b0) * NH;
    const float bh = bhn_s[tx];
    const int hbase = 4 * ty;

    for (int t = 0; t < NT; t++) {
        // per-row done mask -> registers
        float m[4];
#pragma unroll
        for (int i = 0; i < 4; i++)
            m[i] = 1.f - read_done(done,
                       ((size_t)a * NT + t) * NB + b0 + hbase + i, dmode);

        // xi for my (row, col) tile -> registers (12 coalesced LDG)
        const float* xiT = g_xi + (((size_t)a * NT + t) * NB + b0 + hbase) * G3;
        float xr[4], xz[4], xn[4];
#pragma unroll
        for (int i = 0; i < 4; i++) {
            xr[i] = xiT[(size_t)i * G3 + tx];
            xz[i] = xiT[(size_t)i * G3 + 128 + tx];
            xn[i] = xiT[(size_t)i * G3 + 256 + tx];
        }

        // hh = h @ Wh, rows packed in f32x2: a01 = rows (4ty,4ty+1), a23 = (+2,+3)
        ull a01[3] = {0ull, 0ull, 0ull};
        ull a23[3] = {0ull, 0ull, 0ull};
#pragma unroll 4
        for (int k = 0; k < 128; k++) {
            ull h01 = *(const ull*)&h2_s[k * 8 + hbase];
            ull h23 = *(const ull*)&h2_s[k * 8 + hbase + 2];
            float w0 = Wh_s[k * G3 + tx];
            float w1 = Wh_s[k * G3 + 128 + tx];
            float w2 = Wh_s[k * G3 + 256 + tx];
            ull w0p, w1p, w2p;
            PACKF2(w0p, w0, w0);
            PACKF2(w1p, w1, w1);
            PACKF2(w2p, w2, w2);
            FMA2(a01[0], h01, w0p);
            FMA2(a01[1], h01, w1p);
            FMA2(a01[2], h01, w2p);
            FMA2(a23[0], h23, w0p);
            FMA2(a23[1], h23, w1p);
            FMA2(a23[2], h23, w2p);
        }
        float acc[4][3];
#pragma unroll
        for (int g = 0; g < 3; g++) {
            UNPACKF2(acc[0][g], acc[1][g], a01[g]);
            UNPACKF2(acc[2][g], acc[3][g], a23[g]);
        }
        asm volatile("bar.sync %0, 128;" :: "r"(bar) : "memory"); // reads done

        // gates; mask(h)@Wh == m * (h@Wh) since m is per-row scalar
#pragma unroll
        for (int i = 0; i < 4; i++) {
            int r = hbase + i;
            float hprev = m[i] * h2_s[tx * 8 + r];
            float rg = 1.f / (1.f + expf(-(xr[i] + m[i] * acc[i][0])));
            float zg = 1.f / (1.f + expf(-(xz[i] + m[i] * acc[i][1])));
            float ng = tanhf(xn[i] + rg * (m[i] * acc[i][2] + bh));
            float hnew = (1.f - zg) * ng + zg * hprev;
            h2_s[tx * 8 + r] = hnew;
            ysA[((size_t)t * NB + r) * NH + tx] = hnew;
        }
        asm volatile("bar.sync %0, 128;" :: "r"(bar) : "memory"); // writes done
    }

    __syncthreads();
    // final hidden state (col-major smem -> row-major gmem, coalesced stores)
    for (int i = tid; i < 1024; i += 256) {
        int r = i >> 7, c = i & 127;
        out[O_HT + ((size_t)a * NB + b0 + r) * NH + c] = h2_s[c * 8 + r];
    }
}

// ---------------------------------------------------------------------------
// K3: heads.
// ---------------------------------------------------------------------------
__global__ void __launch_bounds__(256)
k_heads(const float* __restrict__ Wa1, const float* __restrict__ ba1,
        const float* __restrict__ Wa2, const float* __restrict__ ba2,
        const float* __restrict__ Wc1, const float* __restrict__ bc1,
        const float* __restrict__ Wc2, const float* __restrict__ bc2,
        const float* __restrict__ log_std, float* __restrict__ out)
{
    extern __shared__ float sm[];
    float* ys_s  = sm;                    // 64*132
    float* act_s = ys_s + 64 * 132;       // 64*132
    float* w_s   = act_s + 64 * 132;      // 128*64
    float* wsm_s = w_s + 128 * 64;        // 1024

    const int a   = blockIdx.y;
    const int r0  = blockIdx.x * 64;
    const int tid = threadIdx.x;
    const int ty  = tid >> 4, tx = tid & 15;

    if (blockIdx.x == 0 && blockIdx.y == 0 && tid < NA * NACT)
        out[O_STD + tid] = expf(log_std[tid]);

    const float* ysA = g_ys + ((size_t)a * NT * NB + r0) * NH;
    for (int i = tid; i < 64 * 32; i += 256) {
        int r = i >> 5, c4 = i & 31;
        ((float4*)&ys_s[r * 132])[c4] = ((const float4*)&ysA[(size_t)r * 128])[c4];
    }

    const float* Wa1A = Wa1 + (size_t)a * 128 * 128;
    for (int cc = 0; cc < 2; cc++) {
        __syncthreads();
        for (int i = tid; i < 128 * 16; i += 256) {
            int k = i >> 4, c4 = i & 15;
            ((float4*)&w_s[k * 64])[c4] = ((const float4*)&Wa1A[k * 128 + cc * 64])[c4];
        }
        __syncthreads();
        float acc[4][4];
        mm_tile2(ys_s, w_s, acc, ty, tx);
#pragma unroll
        for (int i = 0; i < 4; i++)
#pragma unroll
            for (int j = 0; j < 4; j++) {
                int c = cc * 64 + 4 * tx + j;
                act_s[(4 * ty + i) * 132 + c] = tanhf(acc[i][j] + ba1[a * 128 + c]);
            }
    }
    __syncthreads();
    for (int i = tid; i < 128 * 2; i += 256)
        ((float4*)wsm_s)[i] = ((const float4*)(Wa2 + (size_t)a * 128 * NACT))[i];
    __syncthreads();
    for (int o = tid; o < 512; o += 256) {
        int r = o >> 3, ac = o & 7;
        float s = ba2[a * NACT + ac];
#pragma unroll 8
        for (int k = 0; k < 128; k++)
            s = fmaf(act_s[r * 132 + k], wsm_s[k * 8 + ac], s);
        out[O_MEAN + ((size_t)a * NT * NB + r0 + r) * NACT + ac] = s;
    }

    const float* Wc1A = Wc1 + (size_t)a * 128 * 128;
    for (int cc = 0; cc < 2; cc++) {
        __syncthreads();
        for (int i = tid; i < 128 * 16; i += 256) {
            int k = i >> 4, c4 = i & 15;
            ((float4*)&w_s[k * 64])[c4] = ((const float4*)&Wc1A[k * 128 + cc * 64])[c4];
        }
        __syncthreads();
        float acc[4][4];
        mm_tile2(ys_s, w_s, acc, ty, tx);
#pragma unroll
        for (int i = 0; i < 4; i++)
#pragma unroll
            for (int j = 0; j < 4; j++) {
                int c = cc * 64 + 4 * tx + j;
                act_s[(4 * ty + i) * 132 + c] = tanhf(acc[i][j] + bc1[a * 128 + c]);
            }
    }
    __syncthreads();
    if (tid < 128) wsm_s[tid] = Wc2[(size_t)a * 128 + tid];
    __syncthreads();
    if (tid < 64) {
        float s = bc2[a];
#pragma unroll 8
        for (int k = 0; k < 128; k++)
            s = fmaf(act_s[tid * 132 + k], wsm_s[k], s);
        out[O_VAL + (size_t)a * NT * NB + r0 + tid] = s;
    }
}

// ---------------------------------------------------------------------------
extern "C" void kernel_launch(void* const* d_in, const int* in_sizes, int n_in,
                              void* d_out, int out_size)
{
    const float* hstate  = (const float*)d_in[0];
    const float* obs     = (const float*)d_in[1];
    // d_in[2] = avail_actions (unused by the reference outputs)
    const float* We      = (const float*)d_in[3];
    const float* be      = (const float*)d_in[4];
    const float* Wi      = (const float*)d_in[5];
    const float* bi      = (const float*)d_in[6];
    const float* Wh      = (const float*)d_in[7];
    const float* bhn     = (const float*)d_in[8];
    const float* Wa1     = (const float*)d_in[9];
    const float* ba1     = (const float*)d_in[10];
    const float* Wa2     = (const float*)d_in[11];
    const float* ba2     = (const float*)d_in[12];
    const float* log_std = (const float*)d_in[13];
    const float* Wc1     = (const float*)d_in[14];
    const float* bc1     = (const float*)d_in[15];
    const float* Wc2     = (const float*)d_in[16];
    const float* bc2     = (const float*)d_in[17];
    const void*  done    = d_in[18];
    float* out = (float*)d_out;

    const int SMEM1 = (64 * 132 * 2 + 128 * 64) * 4;            // 100352
    const int SMEM2 = (128 * G3 + 128 * 8 + 128) * 4;           // 201216
    const int SMEM3 = (64 * 132 * 2 + 128 * 64 + 1024) * 4;     // 104448

    cudaFuncSetAttribute(k_embed, cudaFuncAttributeMaxDynamicSharedMemorySize, SMEM1);
    cudaFuncSetAttribute(k_gru,   cudaFuncAttributeMaxDynamicSharedMemorySize, SMEM2);
    cudaFuncSetAttribute(k_heads, cudaFuncAttributeMaxDynamicSharedMemorySize, SMEM3);

    const int n_done = in_sizes[18];
    k_dzero<<<1, 1>>>();
    k_ddet<<<32, 256>>>((const unsigned int*)done, n_done / 4);

    k_embed<<<dim3(512, 4), 256, SMEM1>>>(obs, We, be, Wi, bi);
    k_gru  <<<dim3(32, 4),  256, SMEM2>>>(hstate, Wh, bhn, done, out);
    k_heads<<<dim3(512, 4), 256, SMEM3>>>(Wa1, ba1, Wa2, ba2, Wc1, bc1, Wc2, bc2,
                                          log_std, out);
}